// round 8
// baseline (speedup 1.0000x reference)
#include <cuda_runtime.h>
#include <cuda_bf16.h>

// SimSiam loss, algebraically reduced:
//   loss = -0.5 * sum_c( P_c . Z_c  -  sum_{i in c} pn_i.zn_i ) / npairs
// where P_c/Z_c are per-class sums of L2-normalized rows and
// npairs = sum_c m_c*(m_c-1)/2.   O(n*d) work, no 8192x8192 GEMM.
//
// SINGLE LAUNCH, "last-K-done" tail: every block accumulates (phase 1) and
// takes an arrival rank. All but the LAST 16 arrivers exit immediately (no
// spinning). The last 16 — which are by construction nearly the last to
// finish phase 1 — wait the tiny residual for full arrival, then split
// phase 2 (class dots + diag fold + scratch re-zero) 32 classes per block.
// This avoids R6's failure mode (first-launched blocks spinning the whole
// kernel; phase 2 gated on slowest of 1024 CTAs) while still deleting the
// second kernel launch (~3-5us).
//
// Scratch invariant: all accumulated __device__ scratch is ZERO at
// kernel_launch entry (zero at module load; tail blocks re-zero before
// finishing). Deadlock-free: waiters only wait on already-resident blocks
// (grid 1024 <= 8 CTA/SM * 148 SM = 1184, one wave) and non-tail blocks
// exit without waiting.

#define NCLASS 512
#define D      128
#define EPS    1e-8f
#define NTAIL  16                 // tail blocks doing phase 2
#define DPART  64                 // diag partial slots

__device__ float              g_P[NCLASS * D];
__device__ float              g_Z[NCLASS * D];
__device__ int                g_cnt[NCLASS];
__device__ double             g_Dpart[DPART];  // diag partials (accumulated)
__device__ double             g_S;             // final scalar accumulator
__device__ unsigned long long g_pairs;
__device__ unsigned int       g_arrive;        // arrival counter
__device__ unsigned int       g_done;          // tail completion counter

// 128-bit reduction into global memory (sm_90+), no return value.
__device__ __forceinline__ void red_add_v4(float* p, float x, float y, float z, float w) {
    asm volatile("red.global.add.v4.f32 [%0], {%1, %2, %3, %4};"
                 :: "l"(p), "f"(x), "f"(y), "f"(z), "f"(w) : "memory");
}

__global__ void __launch_bounds__(256, 8)
simsiam_kernel(const float* __restrict__ ps,
               const float* __restrict__ zs,
               const void*  __restrict__ tgv,
               float* __restrict__ out,
               int n_rows, unsigned int n_blocks) {
    __shared__ double sdp[8];
    __shared__ int    s_is64;

    int warp_in_blk = threadIdx.x >> 5;
    int lane        = threadIdx.x & 31;
    int warp        = (blockIdx.x * blockDim.x + threadIdx.x) >> 5;

    // ---- targets dtype sniff (warp 0): first 64 int64-view slots (512 B,
    // in-bounds for either dtype; misdetect prob ~2^-576 for random labels).
    if (warp_in_blk == 0) {
        const long long* t64 = (const long long*)tgv;
        int nslots = n_rows / 2;
        int k = (nslots < 64) ? nslots : 64;
        int bad = 0;
        for (int i = lane; i < k; i += 32) {
            long long v = __ldg(&t64[i]);
            if (v < 0 || v >= NCLASS) bad = 1;
        }
        bad = __any_sync(0xFFFFFFFFu, bad);
        if (lane == 0) s_is64 = !bad;
    }
    __syncthreads();
    int is64 = s_is64;

    // ---- phase 1: one warp per row ----
    double diag = 0.0;
    if (warp < n_rows) {
        float4 a = reinterpret_cast<const float4*>(ps)[warp * (D / 4) + lane];
        float4 b = reinterpret_cast<const float4*>(zs)[warp * (D / 4) + lane];

        float sa = a.x * a.x + a.y * a.y + a.z * a.z + a.w * a.w;
        float sb = b.x * b.x + b.y * b.y + b.z * b.z + b.w * b.w;
        float dp = a.x * b.x + a.y * b.y + a.z * b.z + a.w * b.w;

        #pragma unroll
        for (int o = 16; o > 0; o >>= 1) {
            sa += __shfl_xor_sync(0xFFFFFFFFu, sa, o);
            sb += __shfl_xor_sync(0xFFFFFFFFu, sb, o);
            dp += __shfl_xor_sync(0xFFFFFFFFu, dp, o);
        }

        float invp = 1.0f / fmaxf(sqrtf(sa), EPS);
        float invz = 1.0f / fmaxf(sqrtf(sb), EPS);

        int t;
        if (is64) t = (int)reinterpret_cast<const long long*>(tgv)[warp];
        else      t = reinterpret_cast<const int*>(tgv)[warp];

        red_add_v4(&g_P[t * D + lane * 4], a.x * invp, a.y * invp, a.z * invp, a.w * invp);
        red_add_v4(&g_Z[t * D + lane * 4], b.x * invz, b.y * invz, b.z * invz, b.w * invz);

        if (lane == 0) {
            atomicAdd(&g_cnt[t], 1);
            diag = (double)(dp * invp * invz);
        }
    }
    if (lane == 0) sdp[warp_in_blk] = diag;
    __syncthreads();
    if (threadIdx.x == 0) {
        double s = sdp[0] + sdp[1] + sdp[2] + sdp[3]
                 + sdp[4] + sdp[5] + sdp[6] + sdp[7];
        atomicAdd(&g_Dpart[blockIdx.x & (DPART - 1)], s);
    }

    // ---- arrival: take a rank; only the last NTAIL arrivers stay ----
    __shared__ unsigned int s_rank;
    if (threadIdx.x == 0) {
        __threadfence();                       // publish phase-1 writes
        s_rank = atomicAdd(&g_arrive, 1u);
    }
    __syncthreads();
    unsigned int rank = s_rank;
    if (rank < n_blocks - NTAIL) return;       // most blocks exit, no spin

    if (threadIdx.x == 0) {
        // short residual wait: at most NTAIL-1 blocks still running
        while (*(volatile unsigned int*)&g_arrive < n_blocks) __nanosleep(32);
        __threadfence();                       // acquire all blocks' writes
    }
    __syncthreads();

    // ---- phase 2: 16 tail blocks, 32 classes each ----
    int slot = (int)(rank - (n_blocks - NTAIL));     // 0..15
    int cbase = slot * (NCLASS / NTAIL);             // 32 classes per block
    // thread t: class cbase + (t>>3), float4 chunk (t&7)*4 .. +3
    int c    = cbase + (threadIdx.x >> 3);
    int ch   = (threadIdx.x & 7) * 4;
    int idx  = c * (D / 4) + ch;

    float dot = 0.f;
    float4 zero4 = make_float4(0.f, 0.f, 0.f, 0.f);
    #pragma unroll
    for (int j = 0; j < 4; j++) {
        float4 p = reinterpret_cast<const float4*>(g_P)[idx + j];
        float4 z = reinterpret_cast<const float4*>(g_Z)[idx + j];
        dot += p.x * z.x + p.y * z.y + p.z * z.z + p.w * z.w;
        reinterpret_cast<float4*>(g_P)[idx + j] = zero4;   // re-zero scratch
        reinterpret_cast<float4*>(g_Z)[idx + j] = zero4;
    }
    // flat sum across warp (per-class identity not needed for S)
    #pragma unroll
    for (int o = 16; o > 0; o >>= 1)
        dot += __shfl_xor_sync(0xFFFFFFFFu, dot, o);

    // pair counts: threads 0..31 own one class each
    unsigned long long pr = 0ull;
    if (threadIdx.x < NCLASS / NTAIL) {
        int cc = cbase + threadIdx.x;
        unsigned long long m = (unsigned long long)g_cnt[cc];
        pr = m * (m - 1ull) / 2ull;
        g_cnt[cc] = 0;
    }
    if (threadIdx.x < 32) {
        #pragma unroll
        for (int o = 16; o > 0; o >>= 1)
            pr += __shfl_xor_sync(0xFFFFFFFFu, pr, o);
    }

    // diag partials: this block folds DPART/NTAIL = 4 slots
    double dsum = 0.0;
    if (threadIdx.x < DPART / NTAIL) {
        dsum = g_Dpart[slot * (DPART / NTAIL) + threadIdx.x];
        g_Dpart[slot * (DPART / NTAIL) + threadIdx.x] = 0.0;
    }
    if (threadIdx.x < 32) {
        #pragma unroll
        for (int o = 2; o > 0; o >>= 1)
            dsum += __shfl_xor_sync(0xFFFFFFFFu, dsum, o);
    }

    __shared__ double             swd[8];
    __shared__ unsigned long long swp;
    __shared__ double             swdiag;
    if (lane == 0) swd[warp_in_blk] = (double)dot;
    if (threadIdx.x == 0) { swp = pr; swdiag = dsum; }
    __syncthreads();

    if (threadIdx.x == 0) {
        double s = swd[0] + swd[1] + swd[2] + swd[3]
                 + swd[4] + swd[5] + swd[6] + swd[7] - swdiag;
        atomicAdd(&g_S, s);                          // 16 atomics total
        atomicAdd(&g_pairs, swp);
        __threadfence();
        unsigned int done = atomicAdd(&g_done, 1u);
        if (done == (unsigned int)(NTAIL - 1)) {
            double np = (g_pairs > 0ull) ? (double)g_pairs : 1.0;
            out[0] = (float)(-0.5 * g_S / np);
            g_S = 0.0; g_pairs = 0ull;
            g_arrive = 0u; g_done = 0u;
        }
    }
}

// ---------------------------------------------------------------------------
extern "C" void kernel_launch(void* const* d_in, const int* in_sizes, int n_in,
                              void* d_out, int out_size) {
    const float* ps  = (const float*)d_in[0];
    const float* zs  = (const float*)d_in[1];
    const void*  tgt = d_in[2];
    float*       out = (float*)d_out;

    int n_rows = in_sizes[0] / D;               // 8192
    unsigned int n_blocks = (n_rows + 7) / 8;   // 1024

    simsiam_kernel<<<n_blocks, 256>>>(ps, zs, tgt, out, n_rows, n_blocks);
}

// round 9
// speedup vs baseline: 1.2783x; 1.2783x over previous
#include <cuda_runtime.h>
#include <cuda_bf16.h>

// SimSiam loss, algebraically reduced:
//   loss = -0.5 * sum_c( P_c . Z_c  -  sum_{i in c} pn_i.zn_i ) / npairs
// where P_c/Z_c are per-class sums of L2-normalized rows and
// npairs = sum_c m_c*(m_c-1)/2.   O(n*d) work, no 8192x8192 GEMM.
//
// TWO KERNELS — both fused variants (R6/R8) measured ~21us vs 12.3us for
// the split version: per-block gpu-scope fences with in-flight REDs plus
// slowest-CTA gating cost more than a graph-internal launch boundary.
//
// Pair count is accumulated INCREMENTALLY in accum: atomicAdd(&cnt,1)
// returns old m, and sum of old m over a class = m(m-1)/2. So final never
// reads g_cnt (only zeros it).
//
// Scratch invariant: all accumulated __device__ scratch is ZERO at
// kernel_launch entry (zero at module load; final_kernel restores it).

#define NCLASS 512
#define D      128
#define EPS    1e-8f
#define FBLK   64          // final_kernel grid size / partial-slot count

__device__ float              g_P[NCLASS * D];
__device__ float              g_Z[NCLASS * D];
__device__ int                g_cnt[NCLASS];
__device__ double             g_Dpart[FBLK];     // diag partials
__device__ unsigned long long g_PairPart[FBLK];  // incremental pair partials
__device__ double             g_S;               // final scalar accumulator
__device__ unsigned long long g_pairs;
__device__ unsigned int       g_done;

// 128-bit reduction into global memory (sm_90+), no return value.
__device__ __forceinline__ void red_add_v4(float* p, float x, float y, float z, float w) {
    asm volatile("red.global.add.v4.f32 [%0], {%1, %2, %3, %4};"
                 :: "l"(p), "f"(x), "f"(y), "f"(z), "f"(w) : "memory");
}

// ---------------------------------------------------------------------------
// One warp per row: float4 loads, warp-reduce norms + dot, scatter normalized
// rows into per-class sums with 128-bit vector atomics. In-block dtype sniff:
// warp 0 reads the first 64 int64-view slots (512 B, in-bounds either way);
// an int32 buffer misdetects only if 64 consecutive odd labels are 0.
__global__ void accum_kernel(const float* __restrict__ ps,
                             const float* __restrict__ zs,
                             const void*  __restrict__ tgv,
                             int n_rows) {
    __shared__ double       sdp[8];
    __shared__ unsigned int spr[8];
    __shared__ int          s_is64;

    int warp_in_blk = threadIdx.x >> 5;
    int lane        = threadIdx.x & 31;
    int warp        = (blockIdx.x * blockDim.x + threadIdx.x) >> 5;

    if (warp_in_blk == 0) {
        const long long* t64 = (const long long*)tgv;
        int nslots = n_rows / 2;
        int k = (nslots < 64) ? nslots : 64;
        int bad = 0;
        for (int i = lane; i < k; i += 32) {
            long long v = __ldg(&t64[i]);
            if (v < 0 || v >= NCLASS) bad = 1;
        }
        bad = __any_sync(0xFFFFFFFFu, bad);
        if (lane == 0) s_is64 = !bad;
    }
    __syncthreads();
    int is64 = s_is64;

    double       diag = 0.0;
    unsigned int prow = 0u;
    if (warp < n_rows) {
        float4 a = reinterpret_cast<const float4*>(ps)[warp * (D / 4) + lane];
        float4 b = reinterpret_cast<const float4*>(zs)[warp * (D / 4) + lane];

        float sa = a.x * a.x + a.y * a.y + a.z * a.z + a.w * a.w;
        float sb = b.x * b.x + b.y * b.y + b.z * b.z + b.w * b.w;
        float dp = a.x * b.x + a.y * b.y + a.z * b.z + a.w * b.w;

        #pragma unroll
        for (int o = 16; o > 0; o >>= 1) {
            sa += __shfl_xor_sync(0xFFFFFFFFu, sa, o);
            sb += __shfl_xor_sync(0xFFFFFFFFu, sb, o);
            dp += __shfl_xor_sync(0xFFFFFFFFu, dp, o);
        }

        float invp = 1.0f / fmaxf(sqrtf(sa), EPS);
        float invz = 1.0f / fmaxf(sqrtf(sb), EPS);

        int t;
        if (is64) t = (int)reinterpret_cast<const long long*>(tgv)[warp];
        else      t = reinterpret_cast<const int*>(tgv)[warp];

        red_add_v4(&g_P[t * D + lane * 4], a.x * invp, a.y * invp, a.z * invp, a.w * invp);
        red_add_v4(&g_Z[t * D + lane * 4], b.x * invz, b.y * invz, b.z * invz, b.w * invz);

        if (lane == 0) {
            // old count m: summing m over a class's rows gives m(m-1)/2
            prow = (unsigned int)atomicAdd(&g_cnt[t], 1);
            diag = (double)(dp * invp * invz);
        }
    }
    if (lane == 0) { sdp[warp_in_blk] = diag; spr[warp_in_blk] = prow; }
    __syncthreads();
    if (threadIdx.x == 0) {
        double s = sdp[0] + sdp[1] + sdp[2] + sdp[3]
                 + sdp[4] + sdp[5] + sdp[6] + sdp[7];
        unsigned int pr = spr[0] + spr[1] + spr[2] + spr[3]
                        + spr[4] + spr[5] + spr[6] + spr[7];
        int slot = blockIdx.x & (FBLK - 1);           // 64-way spread
        atomicAdd(&g_Dpart[slot], s);
        atomicAdd(&g_PairPart[slot], (unsigned long long)pr);
    }
}

// ---------------------------------------------------------------------------
// Per-class dot (warp per class, 8 classes/block); block reduce -> ONE double
// atomic + one u64 atomic per block (64 each total); fold this block's
// Dpart/PairPart slot locally; re-zero all owned scratch; last-block epilogue.
__global__ void final_kernel(float* __restrict__ out) {
    __shared__ double sdot[8];

    int lane = threadIdx.x & 31;
    int wid  = threadIdx.x >> 5;                 // 0..7
    int c    = blockIdx.x * 8 + wid;
    int idx  = c * (D / 4) + lane;

    float4 p = reinterpret_cast<const float4*>(g_P)[idx];
    float4 z = reinterpret_cast<const float4*>(g_Z)[idx];
    float dot = p.x * z.x + p.y * z.y + p.z * z.z + p.w * z.w;
    #pragma unroll
    for (int o = 16; o > 0; o >>= 1)
        dot += __shfl_xor_sync(0xFFFFFFFFu, dot, o);
    if (lane == 0) sdot[wid] = (double)dot;

    // Re-zero owned scratch (restores launch-entry invariant).
    float4 zero4 = make_float4(0.f, 0.f, 0.f, 0.f);
    reinterpret_cast<float4*>(g_P)[idx] = zero4;
    reinterpret_cast<float4*>(g_Z)[idx] = zero4;
    if (threadIdx.x < 8) g_cnt[blockIdx.x * 8 + threadIdx.x] = 0;

    __syncthreads();
    if (threadIdx.x == 0) {
        double s = sdot[0] + sdot[1] + sdot[2] + sdot[3]
                 + sdot[4] + sdot[5] + sdot[6] + sdot[7]
                 - g_Dpart[blockIdx.x];              // fold diag partial
        unsigned long long pr = g_PairPart[blockIdx.x];
        g_Dpart[blockIdx.x]    = 0.0;                // re-zero scratch
        g_PairPart[blockIdx.x] = 0ull;
        atomicAdd(&g_S, s);                          // 64 atomics total
        atomicAdd(&g_pairs, pr);
        __threadfence();
        unsigned int done = atomicAdd(&g_done, 1u);
        if (done == (unsigned int)(FBLK - 1)) {
            double np = (g_pairs > 0ull) ? (double)g_pairs : 1.0;
            out[0] = (float)(-0.5 * g_S / np);
            g_S = 0.0; g_pairs = 0ull; g_done = 0u;
        }
    }
}

// ---------------------------------------------------------------------------
extern "C" void kernel_launch(void* const* d_in, const int* in_sizes, int n_in,
                              void* d_out, int out_size) {
    const float* ps  = (const float*)d_in[0];
    const float* zs  = (const float*)d_in[1];
    const void*  tgt = d_in[2];
    float*       out = (float*)d_out;

    int n_rows = in_sizes[0] / D;   // 8192

    accum_kernel<<<(n_rows + 7) / 8, 256>>>(ps, zs, tgt, n_rows);
    final_kernel<<<FBLK, 256>>>(out);
}